// round 1
// baseline (speedup 1.0000x reference)
#include <cuda_runtime.h>
#include <cuda_bf16.h>
#include <math.h>

// ---------------------------------------------------------------------------
// Problem constants
//   x: (8,16,3,84,84)  B=8 T=16  -> BT=128 frames
//   enc: 3->64 (pool), 64->128 (pool), 128->256    @84/42/21
//   ConvLSTM: depthwise 3x3 g=512, pointwise 512->1024, gates
//   dec: up2 conv 256->128 @42, up2 conv 128->64 @84, 1x1 64->1
//   outputs: out (8,16,1,84,84), h (8,256,21,21), c (8,256,21,21)
// ---------------------------------------------------------------------------

#define BT   128
#define BB   8
#define TT   16
#define HD   256
#define NP2  441      // 21*21
#define NP1  1764     // 42*42
#define NP0  7056     // 84*84
#define OUTN 903168   // 128*7056 == 8*256*441

// Scratch (module-static device memory; allocation-free at run time)
__device__ float g_e1 [BT * 64  * NP1];   // after enc1+pool  [n][64][42][42]
__device__ float g_e2 [BT * 128 * NP2];   // after enc2+pool  [n][128][21][21]
__device__ float g_feat[BT * 256 * NP2];  // after enc3       [n][256][21][21]
__device__ float g_gdw[BB * 512 * NP2];   // depthwise output per step
__device__ float g_hs [BT * 256 * NP2];   // all h_t          [b*16+t][256][21][21]
__device__ float g_d1 [BT * 128 * NP1];   // dec1 out
__device__ float g_d2 [BT * 64  * NP0];   // dec2 out
__device__ float g_h  [BB * HD * NP2];
__device__ float g_c  [BB * HD * NP2];

__device__ __forceinline__ float sigm(float x) { return 1.0f / (1.0f + expf(-x)); }

// ---------------------------------------------------------------------------
// zero h / c
// ---------------------------------------------------------------------------
__global__ void k_zero_hc()
{
    int i = blockIdx.x * blockDim.x + threadIdx.x;
    if (i < BB * HD * NP2) { g_h[i] = 0.0f; g_c[i] = 0.0f; }
}

// ---------------------------------------------------------------------------
// enc1: conv3x3 3->64 + bias + relu + maxpool2.  84x84 -> pooled 42x42
// block: 448 threads = 21x21 pooled tile; grid (4 tiles, 1, 128 frames)
// ---------------------------------------------------------------------------
__global__ void __launch_bounds__(448) k_enc1(
    const float* __restrict__ x, const float* __restrict__ w,
    const float* __restrict__ bias, float* __restrict__ out)
{
    __shared__ float s_in[3 * 44 * 44];                 // input region (44x44)
    __shared__ __align__(16) float s_w[3 * 9 * 64];     // [ci][k][co]

    const int n   = blockIdx.z;
    const int bx  = blockIdx.x;
    const int py0 = (bx >> 1) * 21;      // pooled tile origin
    const int px0 = (bx & 1) * 21;
    const int oy0 = py0 * 2;             // conv-space origin
    const int ox0 = px0 * 2;
    const int tid = threadIdx.x;

    const float* xn = x + (size_t)n * 3 * NP0;

    for (int idx = tid; idx < 3 * 44 * 44; idx += 448) {
        int ci = idx / 1936, rem = idx % 1936;
        int r = rem / 44, c = rem % 44;
        int gy = oy0 - 1 + r, gx = ox0 - 1 + c;
        float v = 0.0f;
        if (gy >= 0 && gy < 84 && gx >= 0 && gx < 84)
            v = xn[(size_t)ci * NP0 + gy * 84 + gx];
        s_in[idx] = v;
    }
    for (int idx = tid; idx < 3 * 9 * 64; idx += 448) {
        int ci = idx / (9 * 64); int k = (idx % (9 * 64)) / 64; int co = idx % 64;
        s_w[idx] = w[((size_t)co * 3 + ci) * 9 + k];
    }
    __syncthreads();
    if (tid >= 441) return;

    const int ty = tid / 21, tx = tid % 21;
    const int by = 2 * ty, bxp = 2 * tx;

    for (int cg = 0; cg < 8; cg++) {
        float acc[8][4];
        #pragma unroll
        for (int j = 0; j < 8; j++) { acc[j][0]=acc[j][1]=acc[j][2]=acc[j][3]=0.f; }
        #pragma unroll
        for (int ci = 0; ci < 3; ci++) {
            const float* si = &s_in[ci * 1936];
            #pragma unroll
            for (int k = 0; k < 9; k++) {
                int dy = k / 3, dx = k % 3;
                const float* p0 = si + (by + dy) * 44 + (bxp + dx);
                float v00 = p0[0], v01 = p0[1], v10 = p0[44], v11 = p0[45];
                float4 wA = *(const float4*)&s_w[(ci * 9 + k) * 64 + cg * 8];
                float4 wB = *(const float4*)&s_w[(ci * 9 + k) * 64 + cg * 8 + 4];
                float wv[8] = {wA.x, wA.y, wA.z, wA.w, wB.x, wB.y, wB.z, wB.w};
                #pragma unroll
                for (int j = 0; j < 8; j++) {
                    acc[j][0] += v00 * wv[j];
                    acc[j][1] += v01 * wv[j];
                    acc[j][2] += v10 * wv[j];
                    acc[j][3] += v11 * wv[j];
                }
            }
        }
        #pragma unroll
        for (int j = 0; j < 8; j++) {
            int co = cg * 8 + j;
            float m = fmaxf(fmaxf(acc[j][0], acc[j][1]), fmaxf(acc[j][2], acc[j][3]));
            m = fmaxf(m + bias[co], 0.0f);
            out[(((size_t)n * 64 + co) * 42 + py0 + ty) * 42 + px0 + tx] = m;
        }
    }
}

// ---------------------------------------------------------------------------
// generic conv3x3 + bias + relu (+pool / +fused 2x upsample)
// thread computes a 2x2 conv-output micro-tile for 8 output channels.
// block: 448 threads = 21x21 micro-tiles = 42x42 conv outputs.
// grid: (spatial tiles, Cout/8, BT)
// ---------------------------------------------------------------------------
template<bool POOL, bool UP>
__global__ void __launch_bounds__(448) k_conv_pair(
    const float* __restrict__ in, const float* __restrict__ w,
    const float* __restrict__ bias, float* __restrict__ out,
    int Cin, int Cout, int Hc, int nTilesX)
{
    const int CC = 4;
    __shared__ float s_in[CC * 44 * 44];
    __shared__ __align__(16) float s_w[CC * 9 * 8];

    const int n   = blockIdx.z;
    const int coB = blockIdx.y * 8;
    const int tY  = blockIdx.x / nTilesX;
    const int tX  = blockIdx.x % nTilesX;
    const int oy0 = tY * 42, ox0 = tX * 42;
    const int inH = UP ? (Hc >> 1) : Hc;
    const int tid = threadIdx.x;
    const int ty = tid / 21, tx = tid % 21;
    const int by = 2 * ty, bxp = 2 * tx;

    float acc[8][4];
    #pragma unroll
    for (int j = 0; j < 8; j++) { acc[j][0]=acc[j][1]=acc[j][2]=acc[j][3]=0.f; }

    const float* inN = in + (size_t)n * Cin * inH * inH;

    for (int cc = 0; cc < Cin; cc += CC) {
        for (int idx = tid; idx < CC * 44 * 44; idx += 448) {
            int ci = idx / 1936, rem = idx % 1936;
            int r = rem / 44, c = rem % 44;
            int gy = oy0 - 1 + r, gx = ox0 - 1 + c;
            float v = 0.0f;
            if (gy >= 0 && gy < Hc && gx >= 0 && gx < Hc) {
                int sy = UP ? (gy >> 1) : gy;
                int sx = UP ? (gx >> 1) : gx;
                v = inN[((size_t)(cc + ci) * inH + sy) * inH + sx];
            }
            s_in[idx] = v;
        }
        for (int idx = tid; idx < CC * 9 * 8; idx += 448) {
            int ci = idx / 72; int k = (idx % 72) / 8; int co = idx % 8;
            s_w[idx] = w[((size_t)(coB + co) * Cin + (cc + ci)) * 9 + k];
        }
        __syncthreads();
        if (tid < 441) {
            #pragma unroll
            for (int ci = 0; ci < CC; ci++) {
                const float* si = &s_in[ci * 1936];
                #pragma unroll
                for (int k = 0; k < 9; k++) {
                    int dy = k / 3, dx = k % 3;
                    const float* p0 = si + (by + dy) * 44 + (bxp + dx);
                    float v00 = p0[0], v01 = p0[1], v10 = p0[44], v11 = p0[45];
                    float4 wA = *(const float4*)&s_w[(ci * 9 + k) * 8];
                    float4 wB = *(const float4*)&s_w[(ci * 9 + k) * 8 + 4];
                    float wv[8] = {wA.x, wA.y, wA.z, wA.w, wB.x, wB.y, wB.z, wB.w};
                    #pragma unroll
                    for (int j = 0; j < 8; j++) {
                        acc[j][0] += v00 * wv[j];
                        acc[j][1] += v01 * wv[j];
                        acc[j][2] += v10 * wv[j];
                        acc[j][3] += v11 * wv[j];
                    }
                }
            }
        }
        __syncthreads();
    }

    if (tid >= 441) return;
    #pragma unroll
    for (int j = 0; j < 8; j++) {
        int co = coB + j;
        float bv = bias[co];
        if (POOL) {
            int Hp = Hc >> 1;
            float m = fmaxf(fmaxf(acc[j][0], acc[j][1]), fmaxf(acc[j][2], acc[j][3]));
            m = fmaxf(m + bv, 0.0f);
            out[(((size_t)n * Cout + co) * Hp + (oy0 >> 1) + ty) * Hp + (ox0 >> 1) + tx] = m;
        } else {
            #pragma unroll
            for (int p = 0; p < 4; p++) {
                int y = oy0 + by + (p >> 1);
                int xx = ox0 + bxp + (p & 1);
                out[(((size_t)n * Cout + co) * Hc + y) * Hc + xx] = fmaxf(acc[j][p] + bv, 0.0f);
            }
        }
    }
}

// ---------------------------------------------------------------------------
// enc3: conv3x3 128->256 + bias + relu @21x21 (no pool)
// thread = 1 pixel, 16 output channels per block. grid (16, 128)
// ---------------------------------------------------------------------------
__global__ void __launch_bounds__(448) k_enc3(
    const float* __restrict__ in, const float* __restrict__ w,
    const float* __restrict__ bias, float* __restrict__ out)
{
    const int CC = 16;
    __shared__ float s_in[CC * 23 * 23];
    __shared__ __align__(16) float s_w[CC * 9 * 16];

    const int coB = blockIdx.x * 16;
    const int n   = blockIdx.y;
    const int tid = threadIdx.x;
    const int y = tid / 21, x = tid % 21;

    float acc[16];
    #pragma unroll
    for (int j = 0; j < 16; j++) acc[j] = 0.0f;

    const float* inN = in + (size_t)n * 128 * NP2;

    for (int cc = 0; cc < 128; cc += CC) {
        for (int idx = tid; idx < CC * 529; idx += 448) {
            int ci = idx / 529, rem = idx % 529;
            int r = rem / 23, c = rem % 23;
            int gy = r - 1, gx = c - 1;
            float v = 0.0f;
            if (gy >= 0 && gy < 21 && gx >= 0 && gx < 21)
                v = inN[(size_t)(cc + ci) * NP2 + gy * 21 + gx];
            s_in[idx] = v;
        }
        for (int idx = tid; idx < CC * 9 * 16; idx += 448) {
            int ci = idx / 144; int k = (idx % 144) / 16; int co = idx % 16;
            s_w[idx] = w[((size_t)(coB + co) * 128 + (cc + ci)) * 9 + k];
        }
        __syncthreads();
        if (tid < 441) {
            #pragma unroll
            for (int ci = 0; ci < CC; ci++) {
                const float* si = &s_in[ci * 529];
                #pragma unroll
                for (int k = 0; k < 9; k++) {
                    int dy = k / 3, dx = k % 3;
                    float v = si[(y + dy) * 23 + (x + dx)];
                    const float* wb = &s_w[(ci * 9 + k) * 16];
                    float4 w0 = *(const float4*)(wb);
                    float4 w1 = *(const float4*)(wb + 4);
                    float4 w2 = *(const float4*)(wb + 8);
                    float4 w3 = *(const float4*)(wb + 12);
                    acc[0] += v * w0.x;  acc[1] += v * w0.y;  acc[2] += v * w0.z;  acc[3] += v * w0.w;
                    acc[4] += v * w1.x;  acc[5] += v * w1.y;  acc[6] += v * w1.z;  acc[7] += v * w1.w;
                    acc[8] += v * w2.x;  acc[9] += v * w2.y;  acc[10]+= v * w2.z;  acc[11]+= v * w2.w;
                    acc[12]+= v * w3.x;  acc[13]+= v * w3.y;  acc[14]+= v * w3.z;  acc[15]+= v * w3.w;
                }
            }
        }
        __syncthreads();
    }

    if (tid >= 441) return;
    #pragma unroll
    for (int j = 0; j < 16; j++) {
        int co = coB + j;
        out[((size_t)n * 256 + co) * NP2 + tid] = fmaxf(acc[j] + bias[co], 0.0f);
    }
}

// ---------------------------------------------------------------------------
// depthwise conv 3x3, groups=512, no bias. input = concat(feat[t], h)
// grid (512 channels, 8 batch); 448 threads (441 pixels)
// ---------------------------------------------------------------------------
__global__ void __launch_bounds__(448) k_dw(
    const float* __restrict__ dww, int t)
{
    __shared__ float s[NP2];
    const int ch = blockIdx.x;
    const int b  = blockIdx.y;
    const int tid = threadIdx.x;

    const float* src = (ch < 256)
        ? &g_feat[((size_t)(b * TT + t) * 256 + ch) * NP2]
        : &g_h[((size_t)b * HD + (ch - 256)) * NP2];

    if (tid < NP2) s[tid] = src[tid];
    __syncthreads();
    if (tid >= NP2) return;

    float wr[9];
    #pragma unroll
    for (int k = 0; k < 9; k++) wr[k] = __ldg(&dww[(size_t)ch * 9 + k]);

    int y = tid / 21, x = tid % 21;
    float acc = 0.0f;
    #pragma unroll
    for (int k = 0; k < 9; k++) {
        int iy = y + k / 3 - 1, ix = x + k % 3 - 1;
        if (iy >= 0 && iy < 21 && ix >= 0 && ix < 21)
            acc += s[iy * 21 + ix] * wr[k];
    }
    g_gdw[((size_t)b * 512 + ch) * NP2 + tid] = acc;
}

// ---------------------------------------------------------------------------
// pointwise 1x1 512->1024 + bias, fused LSTM gate math.
// block computes 4 "co" values (covering gates i/f/o/g at co, co+256, co+512,
// co+768) for all 441 pixels of one batch. grid (64, 8)
// ---------------------------------------------------------------------------
__global__ void __launch_bounds__(448) k_pw_gates(
    const float* __restrict__ pww, const float* __restrict__ pwb, int t)
{
    const int CC = 16;
    __shared__ float s_in[CC * NP2];
    __shared__ __align__(16) float s_w[CC * 16];   // [ci][gate*4+co]

    const int coB = blockIdx.x * 4;
    const int b   = blockIdx.y;
    const int tid = threadIdx.x;

    float ai[4] = {0,0,0,0}, af[4] = {0,0,0,0}, ao[4] = {0,0,0,0}, ag[4] = {0,0,0,0};

    for (int cc = 0; cc < 512; cc += CC) {
        for (int idx = tid; idx < CC * NP2; idx += 448) {
            int ci = idx / NP2, p = idx % NP2;
            s_in[idx] = g_gdw[((size_t)b * 512 + cc + ci) * NP2 + p];
        }
        if (tid < CC * 16) {
            int ci = tid / 16, j = tid % 16;
            int gate = j / 4, co = j % 4;
            s_w[tid] = pww[((size_t)(gate * 256 + coB + co)) * 512 + cc + ci];
        }
        __syncthreads();
        if (tid < NP2) {
            #pragma unroll
            for (int ci = 0; ci < CC; ci++) {
                float v = s_in[ci * NP2 + tid];
                float4 wi = *(const float4*)&s_w[ci * 16];
                float4 wf = *(const float4*)&s_w[ci * 16 + 4];
                float4 wo = *(const float4*)&s_w[ci * 16 + 8];
                float4 wg = *(const float4*)&s_w[ci * 16 + 12];
                ai[0] += v * wi.x; ai[1] += v * wi.y; ai[2] += v * wi.z; ai[3] += v * wi.w;
                af[0] += v * wf.x; af[1] += v * wf.y; af[2] += v * wf.z; af[3] += v * wf.w;
                ao[0] += v * wo.x; ao[1] += v * wo.y; ao[2] += v * wo.z; ao[3] += v * wo.w;
                ag[0] += v * wg.x; ag[1] += v * wg.y; ag[2] += v * wg.z; ag[3] += v * wg.w;
            }
        }
        __syncthreads();
    }

    if (tid >= NP2) return;
    #pragma unroll
    for (int co = 0; co < 4; co++) {
        int cg = coB + co;
        float iv = sigm(ai[co] + pwb[cg]);
        float fv = sigm(af[co] + pwb[256 + cg]);
        float ov = sigm(ao[co] + pwb[512 + cg]);
        float gv = tanhf(ag[co] + pwb[768 + cg]);
        size_t off = ((size_t)b * HD + cg) * NP2 + tid;
        float c2 = fv * g_c[off] + iv * gv;
        float h2 = ov * tanhf(c2);
        g_c[off] = c2;
        g_h[off] = h2;
        g_hs[((size_t)(b * TT + t) * 256 + cg) * NP2 + tid] = h2;
    }
}

// ---------------------------------------------------------------------------
// dec3: 1x1 conv 64->1 + bias. out[n][pix]
// ---------------------------------------------------------------------------
__global__ void k_dec3(const float* __restrict__ w, const float* __restrict__ bias,
                       float* __restrict__ out)
{
    __shared__ float s_w[64];
    if (threadIdx.x < 64) s_w[threadIdx.x] = w[threadIdx.x];
    __syncthreads();

    int idx = blockIdx.x * blockDim.x + threadIdx.x;
    if (idx >= OUTN) return;
    int n = idx / NP0, pix = idx % NP0;
    const float* d = &g_d2[(size_t)n * 64 * NP0 + pix];
    float acc = bias[0];
    #pragma unroll
    for (int c = 0; c < 64; c++) acc += d[(size_t)c * NP0] * s_w[c];
    out[idx] = acc;
}

// copy final h, c into output tail
__global__ void k_copy_hc(float* __restrict__ out)
{
    int i = blockIdx.x * blockDim.x + threadIdx.x;
    if (i < BB * HD * NP2) {
        out[OUTN + i]        = g_h[i];
        out[2 * OUTN + i]    = g_c[i];
    }
}

// ---------------------------------------------------------------------------
extern "C" void kernel_launch(void* const* d_in, const int* in_sizes, int n_in,
                              void* d_out, int out_size)
{
    const float* x      = (const float*)d_in[0];
    const float* enc_w1 = (const float*)d_in[1];
    const float* enc_b1 = (const float*)d_in[2];
    const float* enc_w2 = (const float*)d_in[3];
    const float* enc_b2 = (const float*)d_in[4];
    const float* enc_w3 = (const float*)d_in[5];
    const float* enc_b3 = (const float*)d_in[6];
    const float* dw_w   = (const float*)d_in[7];
    const float* pw_w   = (const float*)d_in[8];
    const float* pw_b   = (const float*)d_in[9];
    const float* dec_w1 = (const float*)d_in[10];
    const float* dec_b1 = (const float*)d_in[11];
    const float* dec_w2 = (const float*)d_in[12];
    const float* dec_b2 = (const float*)d_in[13];
    const float* dec_w3 = (const float*)d_in[14];
    const float* dec_b3 = (const float*)d_in[15];
    float* out = (float*)d_out;

    float *e1, *e2, *feat, *hs, *d1, *d2;
    cudaGetSymbolAddress((void**)&e1,   g_e1);
    cudaGetSymbolAddress((void**)&e2,   g_e2);
    cudaGetSymbolAddress((void**)&feat, g_feat);
    cudaGetSymbolAddress((void**)&hs,   g_hs);
    cudaGetSymbolAddress((void**)&d1,   g_d1);
    cudaGetSymbolAddress((void**)&d2,   g_d2);

    // init h0/c0 = 0
    k_zero_hc<<<(BB * HD * NP2 + 255) / 256, 256>>>();

    // encoder
    k_enc1<<<dim3(4, 1, BT), 448>>>(x, enc_w1, enc_b1, e1);
    k_conv_pair<true,  false><<<dim3(1, 128 / 8, BT), 448>>>(e1, enc_w2, enc_b2, e2, 64, 128, 42, 1);
    k_enc3<<<dim3(256 / 16, BT), 448>>>(e2, enc_w3, enc_b3, feat);

    // ConvLSTM over T=16 steps
    for (int t = 0; t < TT; t++) {
        k_dw<<<dim3(512, BB), 448>>>(dw_w, t);
        k_pw_gates<<<dim3(64, BB), 448>>>(pw_w, pw_b, t);
    }

    // decoder (upsample fused into conv input indexing)
    k_conv_pair<false, true><<<dim3(1, 128 / 8, BT), 448>>>(hs, dec_w1, dec_b1, d1, 256, 128, 42, 1);
    k_conv_pair<false, true><<<dim3(4, 64 / 8, BT), 448>>>(d1, dec_w2, dec_b2, d2, 128, 64, 84, 2);
    k_dec3<<<(OUTN + 255) / 256, 256>>>(dec_w3, dec_b3, out);

    // append final h and c
    if (out_size >= 3 * OUTN)
        k_copy_hc<<<(BB * HD * NP2 + 255) / 256, 256>>>(out);
}

// round 2
// speedup vs baseline: 1.5448x; 1.5448x over previous
#include <cuda_runtime.h>
#include <cuda_bf16.h>
#include <math.h>

// ---------------------------------------------------------------------------
//   x: (8,16,3,84,84)  B=8 T=16  -> BT=128 frames
//   enc: 3->64 (pool), 64->128 (pool), 128->256    @84/42/21
//   ConvLSTM: depthwise 3x3 g=512, pointwise 512->1024, gates
//   dec: up2 conv 256->128 @42, up2 conv 128->64 @84, 1x1 64->1
//   outputs: out (8,16,1,84,84), h (8,256,21,21), c (8,256,21,21)
// ---------------------------------------------------------------------------

#define BT   128
#define BB   8
#define TT   16
#define HD   256
#define NP2  441      // 21*21
#define NP1  1764     // 42*42
#define NP0  7056     // 84*84
#define OUTN 903168   // 128*7056 == 8*256*441

__device__ float g_e1 [BT * 64  * NP1];
__device__ float g_e2 [BT * 128 * NP2];
__device__ float g_feat[BT * 256 * NP2];
__device__ float g_gdw[BB * 512 * NP2];
__device__ float g_hs [BT * 256 * NP2];
__device__ float g_d1 [BT * 128 * NP1];
__device__ float g_d2 [BT * 64  * NP0];
__device__ float g_h  [BB * HD * NP2];
__device__ float g_c  [BB * HD * NP2];

__device__ __forceinline__ float sigm(float x) { return 1.0f / (1.0f + expf(-x)); }

__global__ void k_zero_hc()
{
    int i = blockIdx.x * blockDim.x + threadIdx.x;
    if (i < BB * HD * NP2) { g_h[i] = 0.0f; g_c[i] = 0.0f; }
}

// ---------------------------------------------------------------------------
// enc1: conv3x3 3->64 + bias + relu + maxpool2.  84x84 -> pooled 42x42
// ---------------------------------------------------------------------------
__global__ void __launch_bounds__(448) k_enc1(
    const float* __restrict__ x, const float* __restrict__ w,
    const float* __restrict__ bias, float* __restrict__ out)
{
    __shared__ float s_in[3 * 44 * 44];
    __shared__ __align__(16) float s_w[3 * 9 * 64];

    const int n   = blockIdx.z;
    const int bx  = blockIdx.x;
    const int py0 = (bx >> 1) * 21;
    const int px0 = (bx & 1) * 21;
    const int oy0 = py0 * 2;
    const int ox0 = px0 * 2;
    const int tid = threadIdx.x;

    const float* xn = x + (size_t)n * 3 * NP0;

    for (int idx = tid; idx < 3 * 44 * 44; idx += 448) {
        int ci = idx / 1936, rem = idx % 1936;
        int r = rem / 44, c = rem % 44;
        int gy = oy0 - 1 + r, gx = ox0 - 1 + c;
        float v = 0.0f;
        if (gy >= 0 && gy < 84 && gx >= 0 && gx < 84)
            v = xn[(size_t)ci * NP0 + gy * 84 + gx];
        s_in[idx] = v;
    }
    for (int idx = tid; idx < 3 * 9 * 64; idx += 448) {
        int ci = idx / (9 * 64); int k = (idx % (9 * 64)) / 64; int co = idx % 64;
        s_w[idx] = w[((size_t)co * 3 + ci) * 9 + k];
    }
    __syncthreads();
    if (tid >= 441) return;

    const int ty = tid / 21, tx = tid % 21;
    const int by = 2 * ty, bxp = 2 * tx;

    for (int cg = 0; cg < 8; cg++) {
        float acc[8][4];
        #pragma unroll
        for (int j = 0; j < 8; j++) { acc[j][0]=acc[j][1]=acc[j][2]=acc[j][3]=0.f; }
        #pragma unroll
        for (int ci = 0; ci < 3; ci++) {
            const float* si = &s_in[ci * 1936];
            #pragma unroll
            for (int k = 0; k < 9; k++) {
                int dy = k / 3, dx = k % 3;
                const float* p0 = si + (by + dy) * 44 + (bxp + dx);
                float v00 = p0[0], v01 = p0[1], v10 = p0[44], v11 = p0[45];
                float4 wA = *(const float4*)&s_w[(ci * 9 + k) * 64 + cg * 8];
                float4 wB = *(const float4*)&s_w[(ci * 9 + k) * 64 + cg * 8 + 4];
                float wv[8] = {wA.x, wA.y, wA.z, wA.w, wB.x, wB.y, wB.z, wB.w};
                #pragma unroll
                for (int j = 0; j < 8; j++) {
                    acc[j][0] += v00 * wv[j];
                    acc[j][1] += v01 * wv[j];
                    acc[j][2] += v10 * wv[j];
                    acc[j][3] += v11 * wv[j];
                }
            }
        }
        #pragma unroll
        for (int j = 0; j < 8; j++) {
            int co = cg * 8 + j;
            float m = fmaxf(fmaxf(acc[j][0], acc[j][1]), fmaxf(acc[j][2], acc[j][3]));
            m = fmaxf(m + bias[co], 0.0f);
            out[(((size_t)n * 64 + co) * 42 + py0 + ty) * 42 + px0 + tx] = m;
        }
    }
}

// ---------------------------------------------------------------------------
// enc2: conv3x3 + bias + relu + maxpool2 @42 -> 21.  (generic pooled conv)
// thread = 2x2 conv outputs (one pooled pixel), 8 couts.
// ---------------------------------------------------------------------------
__global__ void __launch_bounds__(448) k_conv_pool(
    const float* __restrict__ in, const float* __restrict__ w,
    const float* __restrict__ bias, float* __restrict__ out,
    int Cin, int Cout, int Hc)
{
    const int CC = 4;
    __shared__ float s_in[CC * 44 * 44];
    __shared__ __align__(16) float s_w[CC * 9 * 8];

    const int n   = blockIdx.z;
    const int coB = blockIdx.y * 8;
    const int tid = threadIdx.x;
    const int ty = tid / 21, tx = tid % 21;
    const int by = 2 * ty, bxp = 2 * tx;

    float acc[8][4];
    #pragma unroll
    for (int j = 0; j < 8; j++) { acc[j][0]=acc[j][1]=acc[j][2]=acc[j][3]=0.f; }

    const float* inN = in + (size_t)n * Cin * Hc * Hc;

    for (int cc = 0; cc < Cin; cc += CC) {
        for (int idx = tid; idx < CC * 44 * 44; idx += 448) {
            int ci = idx / 1936, rem = idx % 1936;
            int r = rem / 44, c = rem % 44;
            int gy = r - 1, gx = c - 1;
            float v = 0.0f;
            if (gy >= 0 && gy < Hc && gx >= 0 && gx < Hc)
                v = inN[((size_t)(cc + ci) * Hc + gy) * Hc + gx];
            s_in[idx] = v;
        }
        for (int idx = tid; idx < CC * 9 * 8; idx += 448) {
            int ci = idx / 72; int k = (idx % 72) / 8; int co = idx % 8;
            s_w[idx] = w[((size_t)(coB + co) * Cin + (cc + ci)) * 9 + k];
        }
        __syncthreads();
        if (tid < 441) {
            #pragma unroll
            for (int ci = 0; ci < CC; ci++) {
                const float* si = &s_in[ci * 1936];
                #pragma unroll
                for (int k = 0; k < 9; k++) {
                    int dy = k / 3, dx = k % 3;
                    const float* p0 = si + (by + dy) * 44 + (bxp + dx);
                    float v00 = p0[0], v01 = p0[1], v10 = p0[44], v11 = p0[45];
                    float4 wA = *(const float4*)&s_w[(ci * 9 + k) * 8];
                    float4 wB = *(const float4*)&s_w[(ci * 9 + k) * 8 + 4];
                    float wv[8] = {wA.x, wA.y, wA.z, wA.w, wB.x, wB.y, wB.z, wB.w};
                    #pragma unroll
                    for (int j = 0; j < 8; j++) {
                        acc[j][0] += v00 * wv[j];
                        acc[j][1] += v01 * wv[j];
                        acc[j][2] += v10 * wv[j];
                        acc[j][3] += v11 * wv[j];
                    }
                }
            }
        }
        __syncthreads();
    }

    if (tid >= 441) return;
    int Hp = Hc >> 1;
    #pragma unroll
    for (int j = 0; j < 8; j++) {
        int co = coB + j;
        float m = fmaxf(fmaxf(acc[j][0], acc[j][1]), fmaxf(acc[j][2], acc[j][3]));
        m = fmaxf(m + bias[co], 0.0f);
        out[(((size_t)n * Cout + co) * Hp + ty) * Hp + tx] = m;
    }
}

// ---------------------------------------------------------------------------
// enc3: conv3x3 128->256 + bias + relu @21x21.
// thread = 1 pixel, 32 output channels; 3x3 input neighborhood in registers.
// Per ci: 9 input LDS + 72 broadcast LDS.128 -> 288 FFMA.
// ---------------------------------------------------------------------------
__global__ void __launch_bounds__(448) k_enc3(
    const float* __restrict__ in, const float* __restrict__ w,
    const float* __restrict__ bias, float* __restrict__ out)
{
    const int CC = 8;
    __shared__ float s_in[CC * 529];
    __shared__ __align__(16) float s_w[CC * 9 * 32];

    const int coB = blockIdx.x * 32;
    const int n   = blockIdx.y;
    const int tid = threadIdx.x;
    const int y = tid / 21, x = tid % 21;

    float acc[32];
    #pragma unroll
    for (int j = 0; j < 32; j++) acc[j] = 0.0f;

    const float* inN = in + (size_t)n * 128 * NP2;

    for (int cc = 0; cc < 128; cc += CC) {
        for (int idx = tid; idx < CC * 529; idx += 448) {
            int ci = idx / 529, rem = idx % 529;
            int r = rem / 23, c = rem % 23;
            int gy = r - 1, gx = c - 1;
            float v = 0.0f;
            if (gy >= 0 && gy < 21 && gx >= 0 && gx < 21)
                v = inN[(size_t)(cc + ci) * NP2 + gy * 21 + gx];
            s_in[idx] = v;
        }
        for (int idx = tid; idx < CC * 9 * 32; idx += 448) {
            int ci = idx / 288; int k = (idx % 288) / 32; int co = idx % 32;
            s_w[idx] = w[((size_t)(coB + co) * 128 + (cc + ci)) * 9 + k];
        }
        __syncthreads();
        if (tid < 441) {
            #pragma unroll
            for (int ci = 0; ci < CC; ci++) {
                const float* si = &s_in[ci * 529 + y * 23 + x];
                float v[9];
                #pragma unroll
                for (int r = 0; r < 3; r++) {
                    v[r*3+0] = si[r*23+0]; v[r*3+1] = si[r*23+1]; v[r*3+2] = si[r*23+2];
                }
                #pragma unroll
                for (int k = 0; k < 9; k++) {
                    float vv = v[k];
                    const float* wb = &s_w[(ci * 9 + k) * 32];
                    #pragma unroll
                    for (int q = 0; q < 8; q++) {
                        float4 wq = *(const float4*)(wb + q * 4);
                        acc[q*4+0] += vv * wq.x;
                        acc[q*4+1] += vv * wq.y;
                        acc[q*4+2] += vv * wq.z;
                        acc[q*4+3] += vv * wq.w;
                    }
                }
            }
        }
        __syncthreads();
    }

    if (tid >= 441) return;
    #pragma unroll
    for (int j = 0; j < 32; j++) {
        int co = coB + j;
        out[((size_t)n * 256 + co) * NP2 + tid] = fmaxf(acc[j] + bias[co], 0.0f);
    }
}

// ---------------------------------------------------------------------------
// decoder: FOLDED upsample(2x nearest) + conv3x3 + bias + relu.
// Each output parity (py,px) needs only a 2x2 tap on the ORIGINAL image:
//   rows: py=0 -> {w0}@y-1, {w1+w2}@y ; py=1 -> {w0+w1}@y, {w2}@y+1  (cols same)
// thread = one original pixel -> 2x2 outputs, 8 couts. 4 taps/parity.
// Per ci: 9 input LDS + 32 broadcast LDS.128 -> 128 FFMA.
// ---------------------------------------------------------------------------
__global__ void __launch_bounds__(448) k_dec_up(
    const float* __restrict__ in, const float* __restrict__ w,
    const float* __restrict__ bias, float* __restrict__ out,
    int Cin, int Cout, int Hin, int nTilesX)
{
    const int CC = 8;
    __shared__ float s_in[CC * 529];
    __shared__ __align__(16) float s_fw[CC * 16 * 8];   // [ci][par*4+tap][co]

    const int n   = blockIdx.z;
    const int coB = blockIdx.y * 8;
    const int tY  = blockIdx.x / nTilesX;
    const int tX  = blockIdx.x % nTilesX;
    const int y0  = tY * 21, x0 = tX * 21;
    const int tid = threadIdx.x;
    const int ty = tid / 21, tx = tid % 21;

    float acc[8][4];
    #pragma unroll
    for (int j = 0; j < 8; j++) { acc[j][0]=acc[j][1]=acc[j][2]=acc[j][3]=0.f; }

    const float* inN = in + (size_t)n * Cin * Hin * Hin;

    for (int cc = 0; cc < Cin; cc += CC) {
        for (int idx = tid; idx < CC * 529; idx += 448) {
            int ci = idx / 529, rem = idx % 529;
            int r = rem / 23, c = rem % 23;
            int gy = y0 - 1 + r, gx = x0 - 1 + c;
            float v = 0.0f;
            if (gy >= 0 && gy < Hin && gx >= 0 && gx < Hin)
                v = inN[((size_t)(cc + ci) * Hin + gy) * Hin + gx];
            s_in[idx] = v;
        }
        // fold 3x3 weights into per-parity 2x2 taps
        for (int idx = tid; idx < CC * 128; idx += 448) {
            int ci = idx >> 7;
            int pt = (idx >> 3) & 15;
            int co = idx & 7;
            int par = pt >> 2, tap = pt & 3;
            int py = par >> 1, px = par & 1, a = tap >> 1, b = tap & 1;
            const float* wb = &w[((size_t)(coB + co) * Cin + cc + ci) * 9];
            int rlo, rhi, clo, chi;
            if (py == 0) { if (a == 0) { rlo = 0; rhi = 0; } else { rlo = 1; rhi = 2; } }
            else         { if (a == 0) { rlo = 0; rhi = 1; } else { rlo = 2; rhi = 2; } }
            if (px == 0) { if (b == 0) { clo = 0; chi = 0; } else { clo = 1; chi = 2; } }
            else         { if (b == 0) { clo = 0; chi = 1; } else { clo = 2; chi = 2; } }
            float s = 0.0f;
            for (int r = rlo; r <= rhi; r++)
                for (int c = clo; c <= chi; c++)
                    s += wb[r * 3 + c];
            s_fw[idx] = s;
        }
        __syncthreads();
        if (tid < 441) {
            #pragma unroll
            for (int ci = 0; ci < CC; ci++) {
                const float* si = &s_in[ci * 529 + ty * 23 + tx];
                float v[3][3];
                #pragma unroll
                for (int r = 0; r < 3; r++) {
                    v[r][0] = si[r*23+0]; v[r][1] = si[r*23+1]; v[r][2] = si[r*23+2];
                }
                const float* fw = &s_fw[ci * 128];
                #pragma unroll
                for (int par = 0; par < 4; par++) {
                    const int py = par >> 1, px = par & 1;
                    #pragma unroll
                    for (int tap = 0; tap < 4; tap++) {
                        const int a = tap >> 1, b = tap & 1;
                        float vv = v[py + a][px + b];
                        float4 wA = *(const float4*)&fw[(par * 4 + tap) * 8];
                        float4 wB = *(const float4*)&fw[(par * 4 + tap) * 8 + 4];
                        acc[0][par] += vv * wA.x;  acc[1][par] += vv * wA.y;
                        acc[2][par] += vv * wA.z;  acc[3][par] += vv * wA.w;
                        acc[4][par] += vv * wB.x;  acc[5][par] += vv * wB.y;
                        acc[6][par] += vv * wB.z;  acc[7][par] += vv * wB.w;
                    }
                }
            }
        }
        __syncthreads();
    }

    if (tid >= 441) return;
    const int Hout = Hin * 2;
    #pragma unroll
    for (int j = 0; j < 8; j++) {
        int co = coB + j;
        float bv = bias[co];
        #pragma unroll
        for (int py = 0; py < 2; py++) {
            float2 o;
            o.x = fmaxf(acc[j][py * 2 + 0] + bv, 0.0f);
            o.y = fmaxf(acc[j][py * 2 + 1] + bv, 0.0f);
            size_t off = (((size_t)n * Cout + co) * Hout + (y0 + ty) * 2 + py) * Hout
                         + (size_t)(x0 + tx) * 2;
            *(float2*)&out[off] = o;
        }
    }
}

// ---------------------------------------------------------------------------
// depthwise conv 3x3, groups=512, no bias. input = concat(feat[t], h)
// ---------------------------------------------------------------------------
__global__ void __launch_bounds__(448) k_dw(
    const float* __restrict__ dww, int t)
{
    __shared__ float s[NP2];
    const int ch = blockIdx.x;
    const int b  = blockIdx.y;
    const int tid = threadIdx.x;

    const float* src = (ch < 256)
        ? &g_feat[((size_t)(b * TT + t) * 256 + ch) * NP2]
        : &g_h[((size_t)b * HD + (ch - 256)) * NP2];

    if (tid < NP2) s[tid] = src[tid];
    __syncthreads();
    if (tid >= NP2) return;

    float wr[9];
    #pragma unroll
    for (int k = 0; k < 9; k++) wr[k] = __ldg(&dww[(size_t)ch * 9 + k]);

    int y = tid / 21, x = tid % 21;
    float acc = 0.0f;
    #pragma unroll
    for (int k = 0; k < 9; k++) {
        int iy = y + k / 3 - 1, ix = x + k % 3 - 1;
        if (iy >= 0 && iy < 21 && ix >= 0 && ix < 21)
            acc += s[iy * 21 + ix] * wr[k];
    }
    g_gdw[((size_t)b * 512 + ch) * NP2 + tid] = acc;
}

// ---------------------------------------------------------------------------
// pointwise 1x1 512->1024 + bias, fused LSTM gate math.
// block covers 8 "co" values (=> gates at co, co+256, co+512, co+768).
// Per ci: 1 input LDS + 8 broadcast LDS.128 -> 32 FFMA.
// ---------------------------------------------------------------------------
__global__ void __launch_bounds__(448) k_pw_gates(
    const float* __restrict__ pww, const float* __restrict__ pwb, int t)
{
    const int CC = 16;
    __shared__ float s_in[CC * NP2];
    __shared__ __align__(16) float s_w[CC * 32];   // [ci][gate*8+co]

    const int coB = blockIdx.x * 8;
    const int b   = blockIdx.y;
    const int tid = threadIdx.x;

    float ai[8], af[8], ao[8], ag[8];
    #pragma unroll
    for (int j = 0; j < 8; j++) { ai[j]=af[j]=ao[j]=ag[j]=0.0f; }

    for (int cc = 0; cc < 512; cc += CC) {
        for (int idx = tid; idx < CC * NP2; idx += 448) {
            int ci = idx / NP2, p = idx % NP2;
            s_in[idx] = g_gdw[((size_t)b * 512 + cc + ci) * NP2 + p];
        }
        for (int idx = tid; idx < CC * 32; idx += 448) {
            int ci = idx >> 5, j = idx & 31;
            int gate = j >> 3, co = j & 7;
            s_w[idx] = pww[((size_t)(gate * 256 + coB + co)) * 512 + cc + ci];
        }
        __syncthreads();
        if (tid < NP2) {
            #pragma unroll
            for (int ci = 0; ci < CC; ci++) {
                float v = s_in[ci * NP2 + tid];
                const float* fw = &s_w[ci * 32];
                float4 i0 = *(const float4*)(fw +  0), i1 = *(const float4*)(fw +  4);
                float4 f0 = *(const float4*)(fw +  8), f1 = *(const float4*)(fw + 12);
                float4 o0 = *(const float4*)(fw + 16), o1 = *(const float4*)(fw + 20);
                float4 g0 = *(const float4*)(fw + 24), g1 = *(const float4*)(fw + 28);
                ai[0]+=v*i0.x; ai[1]+=v*i0.y; ai[2]+=v*i0.z; ai[3]+=v*i0.w;
                ai[4]+=v*i1.x; ai[5]+=v*i1.y; ai[6]+=v*i1.z; ai[7]+=v*i1.w;
                af[0]+=v*f0.x; af[1]+=v*f0.y; af[2]+=v*f0.z; af[3]+=v*f0.w;
                af[4]+=v*f1.x; af[5]+=v*f1.y; af[6]+=v*f1.z; af[7]+=v*f1.w;
                ao[0]+=v*o0.x; ao[1]+=v*o0.y; ao[2]+=v*o0.z; ao[3]+=v*o0.w;
                ao[4]+=v*o1.x; ao[5]+=v*o1.y; ao[6]+=v*o1.z; ao[7]+=v*o1.w;
                ag[0]+=v*g0.x; ag[1]+=v*g0.y; ag[2]+=v*g0.z; ag[3]+=v*g0.w;
                ag[4]+=v*g1.x; ag[5]+=v*g1.y; ag[6]+=v*g1.z; ag[7]+=v*g1.w;
            }
        }
        __syncthreads();
    }

    if (tid >= NP2) return;
    #pragma unroll
    for (int co = 0; co < 8; co++) {
        int cg = coB + co;
        float iv = sigm(ai[co] + pwb[cg]);
        float fv = sigm(af[co] + pwb[256 + cg]);
        float ov = sigm(ao[co] + pwb[512 + cg]);
        float gv = tanhf(ag[co] + pwb[768 + cg]);
        size_t off = ((size_t)b * HD + cg) * NP2 + tid;
        float c2 = fv * g_c[off] + iv * gv;
        float h2 = ov * tanhf(c2);
        g_c[off] = c2;
        g_h[off] = h2;
        g_hs[((size_t)(b * TT + t) * 256 + cg) * NP2 + tid] = h2;
    }
}

// ---------------------------------------------------------------------------
// dec3: 1x1 conv 64->1 + bias. out[n][pix]
// ---------------------------------------------------------------------------
__global__ void k_dec3(const float* __restrict__ w, const float* __restrict__ bias,
                       float* __restrict__ out)
{
    __shared__ float s_w[64];
    if (threadIdx.x < 64) s_w[threadIdx.x] = w[threadIdx.x];
    __syncthreads();

    int idx = blockIdx.x * blockDim.x + threadIdx.x;
    if (idx >= OUTN) return;
    int n = idx / NP0, pix = idx % NP0;
    const float* d = &g_d2[(size_t)n * 64 * NP0 + pix];
    float acc = bias[0];
    #pragma unroll
    for (int c = 0; c < 64; c++) acc += d[(size_t)c * NP0] * s_w[c];
    out[idx] = acc;
}

__global__ void k_copy_hc(float* __restrict__ out)
{
    int i = blockIdx.x * blockDim.x + threadIdx.x;
    if (i < BB * HD * NP2) {
        out[OUTN + i]     = g_h[i];
        out[2 * OUTN + i] = g_c[i];
    }
}

// ---------------------------------------------------------------------------
extern "C" void kernel_launch(void* const* d_in, const int* in_sizes, int n_in,
                              void* d_out, int out_size)
{
    const float* x      = (const float*)d_in[0];
    const float* enc_w1 = (const float*)d_in[1];
    const float* enc_b1 = (const float*)d_in[2];
    const float* enc_w2 = (const float*)d_in[3];
    const float* enc_b2 = (const float*)d_in[4];
    const float* enc_w3 = (const float*)d_in[5];
    const float* enc_b3 = (const float*)d_in[6];
    const float* dw_w   = (const float*)d_in[7];
    const float* pw_w   = (const float*)d_in[8];
    const float* pw_b   = (const float*)d_in[9];
    const float* dec_w1 = (const float*)d_in[10];
    const float* dec_b1 = (const float*)d_in[11];
    const float* dec_w2 = (const float*)d_in[12];
    const float* dec_b2 = (const float*)d_in[13];
    const float* dec_w3 = (const float*)d_in[14];
    const float* dec_b3 = (const float*)d_in[15];
    float* out = (float*)d_out;

    float *e1, *e2, *feat, *hs, *d1, *d2;
    cudaGetSymbolAddress((void**)&e1,   g_e1);
    cudaGetSymbolAddress((void**)&e2,   g_e2);
    cudaGetSymbolAddress((void**)&feat, g_feat);
    cudaGetSymbolAddress((void**)&hs,   g_hs);
    cudaGetSymbolAddress((void**)&d1,   g_d1);
    cudaGetSymbolAddress((void**)&d2,   g_d2);

    k_zero_hc<<<(BB * HD * NP2 + 255) / 256, 256>>>();

    // encoder
    k_enc1<<<dim3(4, 1, BT), 448>>>(x, enc_w1, enc_b1, e1);
    k_conv_pool<<<dim3(1, 128 / 8, BT), 448>>>(e1, enc_w2, enc_b2, e2, 64, 128, 42);
    k_enc3<<<dim3(256 / 32, BT), 448>>>(e2, enc_w3, enc_b3, feat);

    // ConvLSTM over T=16 steps
    for (int t = 0; t < TT; t++) {
        k_dw<<<dim3(512, BB), 448>>>(dw_w, t);
        k_pw_gates<<<dim3(32, BB), 448>>>(pw_w, pw_b, t);
    }

    // decoder with folded nearest-upsample conv
    k_dec_up<<<dim3(1, 128 / 8, BT), 448>>>(hs, dec_w1, dec_b1, d1, 256, 128, 21, 1);
    k_dec_up<<<dim3(4, 64 / 8, BT), 448>>>(d1, dec_w2, dec_b2, d2, 128, 64, 42, 2);
    k_dec3<<<(OUTN + 255) / 256, 256>>>(dec_w3, dec_b3, out);

    if (out_size >= 3 * OUTN)
        k_copy_hc<<<(BB * HD * NP2 + 255) / 256, 256>>>(out);
}